// round 11
// baseline (speedup 1.0000x reference)
#include <cuda_runtime.h>
#include <cuda_bf16.h>

#define BB 16
#define LL 8400
#define NG 32
#define KK 68
#define NTOPK 13
#define EPSV 1e-9f
#define CAND_CAP 1024
#define CPL 20                         // candidates per lane (reg-resident)
#define SELMAX (CPL * 32)              // 640

// flat output offsets (float32 elements), tuple order:
// labels(B,L), bboxes(B,L,4), scores(B,L,1), poses(B,L,K,3), vertices(B,L,K,3),
// rotations(B,L,3,3), gt_index(B,L)
#define O1 134400
#define O2 672000
#define O3 806400
#define O4 28224000
#define O5 55641600
#define O6 56851200

// scratch (static __device__ globals — zero-init at load, self-cleaning across
// graph replays: g_cnt reset by k_sb, g_mask reset by k34, maxima overwritten)
__device__ unsigned int g_mask[BB * LL];   // resolved one-hot bitmask (sparse)
__device__ int          g_maxm[BB * NG];   // per-gt max metric (float bits, >=0)
__device__ int          g_maxiou[BB * NG]; // per-gt max iou    (float bits, >=0)
__device__ int          g_cnt[BB * NG];    // per-gt candidate count
__device__ float        g_cm[BB * NG * CAND_CAP]; // candidate metrics
__device__ int          g_ci[BB * NG * CAND_CAP]; // candidate anchor indices

__device__ __forceinline__ float iou_fn(float gx1, float gy1, float gx2, float gy2,
                                        float px1, float py1, float px2, float py2) {
    float ix1 = fmaxf(gx1, px1), iy1 = fmaxf(gy1, py1);
    float ix2 = fminf(gx2, px2), iy2 = fminf(gy2, py2);
    float ov = fmaxf(ix2 - ix1, 0.f) * fmaxf(iy2 - iy1, 0.f);
    float a1 = fmaxf(gx2 - gx1, 0.f) * fmaxf(gy2 - gy1, 0.f);
    float a2 = fmaxf(px2 - px1, 0.f) * fmaxf(py2 - py1, 0.f);
    return ov / (a1 + a2 - ov + EPSV);
}

__device__ __forceinline__ bool in_gts_fn(float ax, float ay, float4 g) {
    return (ax - g.x > EPSV) && (ay - g.y > EPSV) && (g.z - ax > EPSV) && (g.w - ay > EPSV);
}

// ---------------- K_cand: anchor-keyed candidate building ----------------
// Reads each anchor once; appends (metric, l) to per-gt lists with
// warp-aggregated atomics. Candidate = in_gts && metric > 0.
__global__ void k_cand(const float* __restrict__ ps, const float* __restrict__ pb,
                       const float* __restrict__ ap, const float* __restrict__ gtb) {
    int b = blockIdx.y;
    int l = blockIdx.x * 256 + threadIdx.x;
    __shared__ float4 sg[NG];
    if (threadIdx.x < NG) sg[threadIdx.x] = ((const float4*)gtb)[b * NG + threadIdx.x];
    __syncthreads();
    bool act = (l < LL);
    int lane = threadIdx.x & 31;
    float ax = 0.f, ay = 0.f, sc = 0.f;
    float4 p = make_float4(0.f, 0.f, 0.f, 0.f);
    if (act) {
        float2 apv = ((const float2*)ap)[l];
        ax = apv.x; ay = apv.y;
        int a = b * LL + l;
        p = ((const float4*)pb)[a];
        sc = ps[a];
    }
    for (int i = 0; i < NG; i++) {
        float4 g = sg[i];
        float m = 0.f;
        if (act && in_gts_fn(ax, ay, g)) {
            float iou = iou_fn(g.x, g.y, g.z, g.w, p.x, p.y, p.z, p.w);
            float i2 = iou * iou;
            m = sc * (i2 * i2 * i2);
        }
        unsigned want = __ballot_sync(0xffffffffu, m > 0.f);
        if (want) {
            int gid = b * NG + i;
            int leader = __ffs(want) - 1;
            int base = 0;
            if (lane == leader) base = atomicAdd(&g_cnt[gid], __popc(want));
            base = __shfl_sync(0xffffffffu, base, leader);
            if (m > 0.f) {
                int pos = base + __popc(want & ((1u << lane) - 1u));
                if (pos < CAND_CAP) {
                    g_cm[gid * CAND_CAP + pos] = m;
                    g_ci[gid * CAND_CAP + pos] = l;
                }
            }
        }
    }
}

// ---------------- K_sb: block-per-batch top-13 + resolve + maxima ----------------
// 8 warps x 4 gts. Candidates live in registers (20/lane); selections recorded
// in smem; multi-claim resolution is block-local via amask[8400]; per-gt maxima
// via smem atomicMax then plain global stores (no pre-zero needed).
__global__ void __launch_bounds__(256) k_sb(const float* __restrict__ ps,
                                            const float* __restrict__ pb,
                                            const float* __restrict__ ap,
                                            const float* __restrict__ gtb,
                                            const float* __restrict__ pad) {
    __shared__ unsigned amask[LL];         // 33.6KB
    __shared__ float4 sgt[NG];
    __shared__ int selA[NG * NTOPK];
    __shared__ int selCnt[NG];
    __shared__ int smaxm[NG], smaxiou[NG];
    int b = blockIdx.x;
    int t = threadIdx.x;
    int warp = t >> 5, lane = t & 31;
    for (int j = t; j < LL; j += 256) amask[j] = 0u;
    if (t < NG) {
        sgt[t] = ((const float4*)gtb)[b * NG + t];
        smaxm[t] = 0; smaxiou[t] = 0; selCnt[t] = 0;
    }
    __syncthreads();

    for (int rep = 0; rep < 4; rep++) {
        int gi = warp * 4 + rep;
        int gid = b * NG + gi;
        float padv = pad[gid];
        int p = min(g_cnt[gid], SELMAX);
        if (lane == 0) g_cnt[gid] = 0;     // self-clean for next replay
        if (padv == 0.f) continue;         // topk_mask==0 (uniform over warp)

        float rv[CPL]; int ri[CPL];
        int base = gid * CAND_CAP;
        #pragma unroll
        for (int r = 0; r < CPL; r++) {
            int j = lane + r * 32;
            bool v = (j < p);
            rv[r] = v ? g_cm[base + j] : -1.f;
            ri[r] = v ? g_ci[base + j] : (1 << 30);
        }
        int nsel = min(p, NTOPK);
        int scnt = 0;
        for (int k = 0; k < nsel; k++) {
            float bv = -1.f; int bi = 1 << 30;
            #pragma unroll
            for (int r = 0; r < CPL; r++)
                if (rv[r] > bv || (rv[r] == bv && ri[r] < bi)) { bv = rv[r]; bi = ri[r]; }
            #pragma unroll
            for (int off = 16; off > 0; off >>= 1) {
                float ov = __shfl_down_sync(0xffffffffu, bv, off);
                int oi = __shfl_down_sync(0xffffffffu, bi, off);
                if (ov > bv || (ov == bv && oi < bi)) { bv = ov; bi = oi; }
            }
            bi = __shfl_sync(0xffffffffu, bi, 0);
            #pragma unroll
            for (int r = 0; r < CPL; r++) if (ri[r] == bi) rv[r] = -1.f;  // destroy winner
            if (lane == 0) {
                atomicOr(&amask[bi], 1u << gi);
                selA[gi * NTOPK + scnt] = bi;
            }
            scnt++;
        }
        // fill path: lax.top_k pads with lowest-index zero-value entries
        if (p < NTOPK) {
            int need = NTOPK - p;
            for (int l = 0; need > 0 && l < LL; l++) {
                bool mine = false;
                #pragma unroll
                for (int r = 0; r < CPL; r++) mine |= (ri[r] == l);
                if (!__any_sync(0xffffffffu, mine)) {   // not a positive candidate
                    need--;
                    if (lane == 0) {
                        float2 apv = ((const float2*)ap)[l];
                        if (in_gts_fn(apv.x, apv.y, sgt[gi])) {
                            atomicOr(&amask[l], 1u << gi);
                            selA[gi * NTOPK + scnt] = l;
                            scnt++;
                        }
                    }
                }
            }
            scnt = __shfl_sync(0xffffffffu, scnt, 0);
        }
        if (lane == 0) selCnt[gi] = scnt;
    }
    __syncthreads();

    // phase 2: resolve multi-claims + per-gt maxima over <=416 entries
    const float4* pbb = (const float4*)pb + (size_t)b * LL;
    const float*  psb = ps + (size_t)b * LL;
    for (int e = t; e < NG * NTOPK; e += 256) {
        int gi = e / NTOPK, k = e % NTOPK;
        if (k >= selCnt[gi]) continue;
        int a = selA[e];
        unsigned bits = amask[a];
        float4 pp = pbb[a];
        int i;
        if (__popc(bits) > 1) {
            // one-hot argmax-iou over ALL gts (first-index tiebreak)
            float bv = -1.f; int bq = 0;
            #pragma unroll
            for (int q = 0; q < NG; q++) {
                float4 g = sgt[q];
                float iou = iou_fn(g.x, g.y, g.z, g.w, pp.x, pp.y, pp.z, pp.w);
                if (iou > bv) { bv = iou; bq = q; }
            }
            i = bq;
        } else {
            i = __ffs(bits) - 1;
        }
        g_mask[b * LL + a] = 1u << i;      // duplicates write identical value
        float4 g = sgt[i];
        float iou = iou_fn(g.x, g.y, g.z, g.w, pp.x, pp.y, pp.z, pp.w);
        float i2 = iou * iou;
        float m = psb[a] * (i2 * i2 * i2);
        atomicMax(&smaxm[i], __float_as_int(m));     // >=0: int order == float order
        atomicMax(&smaxiou[i], __float_as_int(iou));
    }
    __syncthreads();
    if (t < NG) {
        g_maxm[b * NG + t] = smaxm[t];     // plain overwrite each replay
        g_maxiou[b * NG + t] = smaxiou[t];
    }
}

// ---------------- K34: warp-per-anchor, all outputs, self-cleaning ----------------
__global__ void __launch_bounds__(256) k34_out(
        const float* __restrict__ ps, const float* __restrict__ pb,
        const float* __restrict__ gtb, const float* __restrict__ gp,
        const float* __restrict__ gv, const float* __restrict__ grot,
        const int* __restrict__ gl, const int* __restrict__ bgp,
        float* __restrict__ out) {
    unsigned a = (blockIdx.x * 256u + threadIdx.x) >> 5;   // anchor = warp id
    int lane = threadIdx.x & 31;
    unsigned bits = g_mask[a];                 // broadcast load (one-hot or 0)
    int b = a / LL;
    int i = bits ? (__ffs(bits) - 1) : 0;      // argmax of all-zero column = 0
    size_t gidx = (size_t)(b * NG + i);

    const float4* Psrc = (const float4*)gp + gidx * 51;
    const float4* Vsrc = (const float4*)gv + gidx * 51;
    float4* Pd = (float4*)(out + O3) + (size_t)a * 51;
    float4* Vd = (float4*)(out + O4) + (size_t)a * 51;

    int c0 = lane, c1 = lane + 32, c2 = lane + 64, c3 = lane + 96;
    float4 v0 = (c0 < 51) ? Psrc[c0] : Vsrc[c0 - 51];
    float4 v1 = (c1 < 51) ? Psrc[c1] : Vsrc[c1 - 51];
    float4 v2 = Vsrc[c2 - 51];
    float4 v3; bool has3 = (c3 < 102);
    float r9 = 0.f;
    if (has3) v3 = Vsrc[c3 - 51];
    if (lane < 9) r9 = grot[gidx * 9 + lane];

    if (c0 < 51) Pd[c0] = v0; else Vd[c0 - 51] = v0;
    if (c1 < 51) Pd[c1] = v1; else Vd[c1 - 51] = v1;
    Vd[c2 - 51] = v2;
    if (has3) Vd[c3 - 51] = v3;
    if (lane < 9) out[O5 + (size_t)a * 9 + lane] = r9;

    if (lane == 0) {
        int lbl = bits ? gl[gidx] : bgp[0];
        float4 gbox = ((const float4*)gtb)[gidx];
        float score = 0.f;
        if (bits) {
            float4 p = ((const float4*)pb)[a];
            float iou = iou_fn(gbox.x, gbox.y, gbox.z, gbox.w, p.x, p.y, p.z, p.w);
            float i2 = iou * iou;
            float m = ps[a] * (i2 * i2 * i2);
            float mm = __int_as_float(g_maxm[gidx]);
            float mi = __int_as_float(g_maxiou[gidx]);
            float am = m / (mm + EPSV) * mi;
            score = (lbl == 0) ? am : 0.f;  // one_hot(lbl, C+1)[..., keep=[0]]
            g_mask[a] = 0u;                 // self-clean for next replay
        }
        out[a] = (float)lbl;                // assigned_labels
        ((float4*)(out + O1))[a] = gbox;    // assigned_bboxes
        out[O2 + a] = score;                // assigned_scores
        out[O6 + a] = (float)gidx;          // assigned_gt_index
    }
}

extern "C" void kernel_launch(void* const* d_in, const int* in_sizes, int n_in,
                              void* d_out, int out_size) {
    const float* ps  = (const float*)d_in[0];  // pred_scores  (B,L,1)
    const float* pb  = (const float*)d_in[1];  // pred_bboxes  (B,L,4)
    const float* ap  = (const float*)d_in[2];  // anchor_points(L,2)
    const int*   gl  = (const int*)  d_in[3];  // gt_labels
    const float* gtb = (const float*)d_in[4];  // gt_bboxes    (B,n,4)
    const float* gp  = (const float*)d_in[5];  // gt_poses     (B,n,K,3)
    const float* gv  = (const float*)d_in[6];  // gt_vertices  (B,n,K,3)
    const float* gr  = (const float*)d_in[7];  // gt_rotations (B,n,3,3)
    const float* pad = (const float*)d_in[8];  // pad_gt_mask  (B,n,1)
    const int*   bg  = (const int*)  d_in[9];  // bg_index scalar
    float* out = (float*)d_out;

    dim3 ga((LL + 255) / 256, BB);
    k_cand<<<ga, 256>>>(ps, pb, ap, gtb);
    k_sb<<<BB, 256>>>(ps, pb, ap, gtb, pad);
    // 134400 anchors = 134400 warps = 16800 blocks of 8 warps, exact
    k34_out<<<16800, 256>>>(ps, pb, gtb, gp, gv, gr, gl, bg, out);
}

// round 14
// speedup vs baseline: 1.3611x; 1.3611x over previous
#include <cuda_runtime.h>
#include <cuda_bf16.h>

#define BB 16
#define LL 8400
#define NG 32
#define KK 68
#define NTOPK 13
#define EPSV 1e-9f
#define CAND_CAP 1024
#define SEL_CAP 640

// flat output offsets (float32 elements), tuple order:
// labels(B,L), bboxes(B,L,4), scores(B,L,1), poses(B,L,K,3), vertices(B,L,K,3),
// rotations(B,L,3,3), gt_index(B,L)
#define O1 134400
#define O2 672000
#define O3 806400
#define O4 28224000
#define O5 55641600
#define O6 56851200

// scratch (static __device__ globals — no runtime allocation)
__device__ unsigned int g_mask[BB * LL];   // per-anchor gt bitmask; resolved in-place by k2
__device__ int          g_maxm[BB * NG];   // per-gt max metric   (float bits, >=0)
__device__ int          g_maxiou[BB * NG]; // per-gt max iou      (float bits, >=0)
__device__ int          g_cnt[BB * NG];    // per-gt candidate count
__device__ float        g_cm[BB * NG * CAND_CAP]; // candidate metrics
__device__ int          g_ci[BB * NG * CAND_CAP]; // candidate anchor indices

__device__ __forceinline__ float iou_fn(float gx1, float gy1, float gx2, float gy2,
                                        float px1, float py1, float px2, float py2) {
    float ix1 = fmaxf(gx1, px1), iy1 = fmaxf(gy1, py1);
    float ix2 = fminf(gx2, px2), iy2 = fminf(gy2, py2);
    float ov = fmaxf(ix2 - ix1, 0.f) * fmaxf(iy2 - iy1, 0.f);
    float a1 = fmaxf(gx2 - gx1, 0.f) * fmaxf(gy2 - gy1, 0.f);
    float a2 = fmaxf(px2 - px1, 0.f) * fmaxf(py2 - py1, 0.f);
    return ov / (a1 + a2 - ov + EPSV);
}

__device__ __forceinline__ bool in_gts_fn(float ax, float ay, float4 g) {
    return (ax - g.x > EPSV) && (ay - g.y > EPSV) && (g.z - ax > EPSV) && (g.w - ay > EPSV);
}

// ---------------- K0: zero scratch ----------------
__global__ void k0_zero() {
    int idx = blockIdx.x * blockDim.x + threadIdx.x;
    int stride = gridDim.x * blockDim.x;
    for (int i = idx; i < BB * LL; i += stride) g_mask[i] = 0u;
    for (int i = idx; i < BB * NG; i += stride) { g_maxm[i] = 0; g_maxiou[i] = 0; g_cnt[i] = 0; }
}

// ---------------- K_cand: anchor-keyed candidate building (128-thr blocks) ----------------
// Reads each anchor once; appends (metric, l) to per-gt lists with
// warp-aggregated atomics. Candidate = in_gts && metric > 0.
__global__ void __launch_bounds__(128) k_cand(const float* __restrict__ ps,
                                              const float* __restrict__ pb,
                                              const float* __restrict__ ap,
                                              const float* __restrict__ gtb) {
    int b = blockIdx.y;
    int l = blockIdx.x * 128 + threadIdx.x;
    __shared__ float4 sg[NG];
    if (threadIdx.x < NG) sg[threadIdx.x] = ((const float4*)gtb)[b * NG + threadIdx.x];
    __syncthreads();
    bool act = (l < LL);
    int lane = threadIdx.x & 31;
    float ax = 0.f, ay = 0.f, sc = 0.f;
    float4 p = make_float4(0.f, 0.f, 0.f, 0.f);
    if (act) {
        float2 apv = ((const float2*)ap)[l];
        ax = apv.x; ay = apv.y;
        int a = b * LL + l;
        p = ((const float4*)pb)[a];
        sc = ps[a];
    }
    for (int i = 0; i < NG; i++) {
        float4 g = sg[i];
        float m = 0.f;
        if (act && in_gts_fn(ax, ay, g)) {
            float iou = iou_fn(g.x, g.y, g.z, g.w, p.x, p.y, p.z, p.w);
            float i2 = iou * iou;
            m = sc * (i2 * i2 * i2);
        }
        unsigned want = __ballot_sync(0xffffffffu, m > 0.f);
        if (want) {
            int gid = b * NG + i;
            int leader = __ffs(want) - 1;
            int base = 0;
            if (lane == leader) base = atomicAdd(&g_cnt[gid], __popc(want));
            base = __shfl_sync(0xffffffffu, base, leader);
            if (m > 0.f) {
                int pos = base + __popc(want & ((1u << lane) - 1u));
                if (pos < CAND_CAP) {
                    g_cm[gid * CAND_CAP + pos] = m;
                    g_ci[gid * CAND_CAP + pos] = l;
                }
            }
        }
    }
}

// ---------------- K_sel: warp-per-gt top-13 over candidate list ----------------
__global__ void __launch_bounds__(128) k_sel(const float* __restrict__ ap,
                                             const float* __restrict__ gtb,
                                             const float* __restrict__ pad) {
    __shared__ float sv[4][SEL_CAP];
    __shared__ int   si[4][SEL_CAP];
    int wl = threadIdx.x >> 5;
    int w  = blockIdx.x * 4 + wl;     // gt id: b*NG+gi
    int lane = threadIdx.x & 31;
    int b  = w >> 5;                  // NG == 32
    int gi = w & 31;
    if (pad[w] == 0.f) return;        // uniform over warp
    int p = min(g_cnt[w], SEL_CAP);
    int base = w * CAND_CAP;
    for (int j = lane; j < p; j += 32) { sv[wl][j] = g_cm[base + j]; si[wl][j] = g_ci[base + j]; }
    __syncwarp();
    unsigned mbase = b * LL;
    int nsel = min(p, NTOPK);
    for (int k = 0; k < nsel; k++) {
        float bv = -1.f; int bi = 1 << 30; int bj = -1;
        for (int j = lane; j < p; j += 32) {
            float v = sv[wl][j]; int idx = si[wl][j];
            if (v > bv || (v == bv && idx < bi)) { bv = v; bi = idx; bj = j; }
        }
        #pragma unroll
        for (int off = 16; off > 0; off >>= 1) {
            float ov = __shfl_down_sync(0xffffffffu, bv, off);
            int oi = __shfl_down_sync(0xffffffffu, bi, off);
            int oj = __shfl_down_sync(0xffffffffu, bj, off);
            if (ov > bv || (ov == bv && oi < bi)) { bv = ov; bi = oi; bj = oj; }
        }
        bj = __shfl_sync(0xffffffffu, bj, 0);
        bi = __shfl_sync(0xffffffffu, bi, 0);
        if (lane == 0) {
            sv[wl][bj] = -1.f;                        // remove selected
            atomicOr(&g_mask[mbase + bi], 1u << gi);  // candidates are in_gts by construction
        }
        __syncwarp();
    }
    if (p < NTOPK && lane == 0) {
        float4 g = ((const float4*)gtb)[w];
        int need = NTOPK - p;
        for (int l = 0; need > 0 && l < LL; l++) {
            bool ispos = false;
            for (int j = 0; j < p; j++) if (si[wl][j] == l) { ispos = true; break; }
            if (!ispos) {
                need--;
                float2 apv = ((const float2*)ap)[l];
                if (in_gts_fn(apv.x, apv.y, g))
                    atomicOr(&g_mask[mbase + l], 1u << gi);
            }
        }
    }
}

// ---------------- K2: resolve multi-claims + per-gt maxima, 4 anchors/thread ----------------
// One uint4 load covers 4 masks; ~95% of threads exit after it. 8400 % 4 == 0
// so all 4 anchors of a thread share one batch. Resolution in-place on g_mask.
__global__ void __launch_bounds__(256) k2_resolve(const float* __restrict__ ps,
                                                  const float* __restrict__ pb,
                                                  const float* __restrict__ gtb) {
    __shared__ float4 sg[BB * NG];   // all 512 gt boxes, 8KB
    for (int j = threadIdx.x; j < BB * NG; j += 256) sg[j] = ((const float4*)gtb)[j];
    __syncthreads();
    int t = blockIdx.x * 256 + threadIdx.x;
    if (t >= BB * LL / 4) return;               // 33600 uint4 units total
    uint4 m4 = ((const uint4*)g_mask)[t];
    if ((m4.x | m4.y | m4.z | m4.w) == 0u) return;
    int a0 = t * 4;
    int b = a0 / LL;                             // same batch for all 4 (8400 % 4 == 0)
    const float4* sgb = sg + b * NG;
    unsigned mm[4] = {m4.x, m4.y, m4.z, m4.w};
    #pragma unroll
    for (int q = 0; q < 4; q++) {
        unsigned bits = mm[q];
        if (!bits) continue;
        int a = a0 + q;
        float4 p = ((const float4*)pb)[a];
        float sc = ps[a];
        int i;
        if (__popc(bits) > 1) {
            // one-hot argmax-iou over ALL gts (first-index tiebreak)
            float bv = -1.f; int bq = 0;
            #pragma unroll
            for (int j = 0; j < NG; j++) {
                float4 g = sgb[j];
                float iou = iou_fn(g.x, g.y, g.z, g.w, p.x, p.y, p.z, p.w);
                if (iou > bv) { bv = iou; bq = j; }
            }
            i = bq;
            g_mask[a] = 1u << i;                 // in-place resolved one-hot
        } else {
            i = __ffs(bits) - 1;
        }
        int gid = b * NG + i;
        float4 g = sgb[i];
        float iou = iou_fn(g.x, g.y, g.z, g.w, p.x, p.y, p.z, p.w);
        float i2 = iou * iou;
        float m = sc * (i2 * i2 * i2);
        atomicMax(&g_maxm[gid], __float_as_int(m));     // >=0: int order == float order
        atomicMax(&g_maxiou[gid], __float_as_int(iou));
    }
}

// ---------------- K34: warp-per-anchor, all outputs ----------------
__global__ void __launch_bounds__(256) k34_out(
        const float* __restrict__ ps, const float* __restrict__ pb,
        const float* __restrict__ gtb, const float* __restrict__ gp,
        const float* __restrict__ gv, const float* __restrict__ grot,
        const int* __restrict__ gl, const int* __restrict__ bgp,
        float* __restrict__ out) {
    unsigned a = (blockIdx.x * 256u + threadIdx.x) >> 5;   // anchor = warp id
    int lane = threadIdx.x & 31;
    unsigned bits = g_mask[a];                 // broadcast load (one-hot or 0)
    int b = a / LL;
    int i = bits ? (__ffs(bits) - 1) : 0;      // argmax of all-zero column = 0
    size_t gidx = (size_t)(b * NG + i);

    const float4* Psrc = (const float4*)gp + gidx * 51;
    const float4* Vsrc = (const float4*)gv + gidx * 51;
    float4* Pd = (float4*)(out + O3) + (size_t)a * 51;
    float4* Vd = (float4*)(out + O4) + (size_t)a * 51;

    int c0 = lane, c1 = lane + 32, c2 = lane + 64, c3 = lane + 96;
    float4 v0 = (c0 < 51) ? Psrc[c0] : Vsrc[c0 - 51];
    float4 v1 = (c1 < 51) ? Psrc[c1] : Vsrc[c1 - 51];
    float4 v2 = Vsrc[c2 - 51];
    float4 v3; bool has3 = (c3 < 102);
    float r9 = 0.f;
    if (has3) v3 = Vsrc[c3 - 51];
    if (lane < 9) r9 = grot[gidx * 9 + lane];

    if (c0 < 51) Pd[c0] = v0; else Vd[c0 - 51] = v0;
    if (c1 < 51) Pd[c1] = v1; else Vd[c1 - 51] = v1;
    Vd[c2 - 51] = v2;
    if (has3) Vd[c3 - 51] = v3;
    if (lane < 9) out[O5 + (size_t)a * 9 + lane] = r9;

    if (lane == 0) {
        int lbl = bits ? gl[gidx] : bgp[0];
        float4 gbox = ((const float4*)gtb)[gidx];
        float score = 0.f;
        if (bits) {
            float4 p = ((const float4*)pb)[a];
            float iou = iou_fn(gbox.x, gbox.y, gbox.z, gbox.w, p.x, p.y, p.z, p.w);
            float i2 = iou * iou;
            float m = ps[a] * (i2 * i2 * i2);
            float mm = __int_as_float(g_maxm[gidx]);
            float mi = __int_as_float(g_maxiou[gidx]);
            float am = m / (mm + EPSV) * mi;
            score = (lbl == 0) ? am : 0.f;  // one_hot(lbl, C+1)[..., keep=[0]]
        }
        out[a] = (float)lbl;                // assigned_labels
        ((float4*)(out + O1))[a] = gbox;    // assigned_bboxes
        out[O2 + a] = score;                // assigned_scores
        out[O6 + a] = (float)gidx;          // assigned_gt_index
    }
}

extern "C" void kernel_launch(void* const* d_in, const int* in_sizes, int n_in,
                              void* d_out, int out_size) {
    const float* ps  = (const float*)d_in[0];  // pred_scores  (B,L,1)
    const float* pb  = (const float*)d_in[1];  // pred_bboxes  (B,L,4)
    const float* ap  = (const float*)d_in[2];  // anchor_points(L,2)
    const int*   gl  = (const int*)  d_in[3];  // gt_labels
    const float* gtb = (const float*)d_in[4];  // gt_bboxes    (B,n,4)
    const float* gp  = (const float*)d_in[5];  // gt_poses     (B,n,K,3)
    const float* gv  = (const float*)d_in[6];  // gt_vertices  (B,n,K,3)
    const float* gr  = (const float*)d_in[7];  // gt_rotations (B,n,3,3)
    const float* pad = (const float*)d_in[8];  // pad_gt_mask  (B,n,1)
    const int*   bg  = (const int*)  d_in[9];  // bg_index scalar
    float* out = (float*)d_out;

    k0_zero<<<132, 256>>>();
    dim3 gc((LL + 127) / 128, BB);              // (66, 16) = 1056 blocks
    k_cand<<<gc, 128>>>(ps, pb, ap, gtb);
    k_sel<<<BB * NG / 4, 128>>>(ap, gtb, pad);
    // ceil(33600 / 256) = 132 blocks; in-kernel bound guards the tail
    k2_resolve<<<(BB * LL / 4 + 255) / 256, 256>>>(ps, pb, gtb);
    // 134400 anchors = 134400 warps = 16800 blocks of 8 warps, exact
    k34_out<<<16800, 256>>>(ps, pb, gtb, gp, gv, gr, gl, bg, out);
}